// round 10
// baseline (speedup 1.0000x reference)
#include <cuda_runtime.h>
#include <cuda_bf16.h>
#include <cstdint>

// Problem constants
#define T_STEPS 500
#define B_SZ    128
#define K_SZ    256
#define F_SZ    512
#define C_SZ    10
#define MROWS   (T_STEPS * B_SZ)   // 64000
#define NEURONS (B_SZ * F_SZ)      // 65536

#define T_SPLIT 400                 // scan overlap split (multiple of 20)

// ---- HMMA GEMM (cols 0..383): CTA 128x128, 8 warps of 64x32, KC=64 ----
#define TM 128
#define TN 128
#define KC 64
#define NCHUNK (K_SZ / KC)   // 4
#define GT 256
#define H_NTILES 3           // cols 0..383

#define PITCHB     144
#define TILEBYTES  (128 * PITCHB)      // 18432
#define A_HI 0
#define A_LO TILEBYTES
#define B_HI (2 * TILEBYTES)
#define B_LO (3 * TILEBYTES)
#define STAGEBYTES (4 * TILEBYTES)     // 73728
#define SMEM_TOTAL (2 * STAGEBYTES)    // 147456

// ---- FFMA GEMM (cols 384..511, exact fp32): CTA 64m x 128n, 128 thr ----
#define FNBASE   384
#define FM       64
#define F_THREADS 128
#define FKC      32
#define FA_PITCH 144                       // 32 f32 = 128B + 16 pad
#define FA_BYTES (FM * FA_PITCH)           // 9216
#define FB_PITCH 512                       // 128 f32, no pad (lane-per-n staging)
#define FB_BYTES (FKC * FB_PITCH)          // 16384
#define FSTAGE   (FA_BYTES + FB_BYTES)     // 25600
#define F_SMEM   (2 * FSTAGE)              // 51200
#define F_BLOCKS (MROWS / FM)              // 1000
#define F_SPLIT  (T_SPLIT * B_SZ / FM)     // 800

// Scratch
__device__ float g_proj[MROWS * F_SZ];            // 131 MB
__device__ float g_counts[NEURONS];
__device__ float g_u[NEURONS];
__device__ float g_tr[NEURONS];
__device__ __nv_bfloat16 g_whi[F_SZ * K_SZ];
__device__ __nv_bfloat16 g_wlo[F_SZ * K_SZ];

// ---------------- helpers ----------------
__device__ __forceinline__ uint32_t smem_u32(const void* p) {
    uint32_t a;
    asm("{ .reg .u64 t; cvta.to.shared.u64 t, %1; cvt.u32.u64 %0, t; }" : "=r"(a) : "l"(p));
    return a;
}
__device__ __forceinline__ void cp_async16(uint32_t dst, const void* src) {
    asm volatile("cp.async.cg.shared.global [%0], [%1], 16;" :: "r"(dst), "l"(src) : "memory");
}
#define CP_COMMIT() asm volatile("cp.async.commit_group;" ::: "memory")

__device__ __forceinline__ void ldmx4(uint32_t* r, uint32_t addr) {
    asm volatile("ldmatrix.sync.aligned.m8n8.x4.shared.b16 {%0,%1,%2,%3}, [%4];"
                 : "=r"(r[0]), "=r"(r[1]), "=r"(r[2]), "=r"(r[3]) : "r"(addr));
}
__device__ __forceinline__ void mma_bf16(float* c, const uint32_t* a, const uint32_t* b) {
    asm volatile(
        "mma.sync.aligned.m16n8k16.row.col.f32.bf16.bf16.f32 "
        "{%0,%1,%2,%3}, {%4,%5,%6,%7}, {%8,%9}, {%0,%1,%2,%3};"
        : "+f"(c[0]), "+f"(c[1]), "+f"(c[2]), "+f"(c[3])
        : "r"(a[0]), "r"(a[1]), "r"(a[2]), "r"(a[3]), "r"(b[0]), "r"(b[1]));
}
__device__ __forceinline__ void split2(float a, float b, uint32_t& hi, uint32_t& lo) {
    __nv_bfloat16 h0 = __float2bfloat16(a), h1 = __float2bfloat16(b);
    __nv_bfloat16 l0 = __float2bfloat16(a - __bfloat162float(h0));
    __nv_bfloat16 l1 = __float2bfloat16(b - __bfloat162float(h1));
    hi = (uint32_t)*(uint16_t*)&h0 | ((uint32_t)*(uint16_t*)&h1 << 16);
    lo = (uint32_t)*(uint16_t*)&l0 | ((uint32_t)*(uint16_t*)&l1 << 16);
}
__device__ __forceinline__ unsigned long long pack2(float lo, float hi) {
    unsigned long long d;
    asm("mov.b64 %0, {%1, %2};" : "=l"(d) : "r"(__float_as_uint(lo)), "r"(__float_as_uint(hi)));
    return d;
}
__device__ __forceinline__ void fma2(unsigned long long& d, unsigned long long a, unsigned long long b) {
    asm("fma.rn.f32x2 %0, %1, %2, %0;" : "+l"(d) : "l"(a), "l"(b));
}
__device__ __forceinline__ void unpack2(unsigned long long v, float& lo, float& hi) {
    unsigned int a, b;
    asm("mov.b64 {%0, %1}, %2;" : "=r"(a), "=r"(b) : "l"(v));
    lo = __uint_as_float(a); hi = __uint_as_float(b);
}

// ---------------- Pass 0: W fp32 -> bf16 hi/lo (tiny) ----------------
__global__ void convert_w_kernel(const float4* __restrict__ wsrc,
                                 uint2* __restrict__ whi, uint2* __restrict__ wlo, int n4)
{
    int i = blockIdx.x * blockDim.x + threadIdx.x;
    if (i >= n4) return;
    float4 v = wsrc[i];
    uint2 ph, pl;
    split2(v.x, v.y, ph.x, pl.x);
    split2(v.z, v.w, ph.y, pl.y);
    whi[i] = ph;
    wlo[i] = pl;
}

// ---------------- HMMA GEMM: proj[:, 0:384] ----------------
__global__ __launch_bounds__(GT, 1)
void snn_gemm_kernel(const float* __restrict__ x, int mbase)
{
    extern __shared__ char smem[];
    const uint32_t sb = smem_u32(smem);
    const int tid  = threadIdx.x;
    const int lane = tid & 31;
    const int wid  = tid >> 5;
    const int wm   = wid >> 2;
    const int wn   = wid & 3;
    const int mtile = blockIdx.x + mbase;
    const int ntile = blockIdx.y;

    const uint32_t laneoff = (uint32_t)((lane & 15) * PITCHB + (lane >> 4) * 16);

    float acc[4][4][4];
    #pragma unroll
    for (int mi = 0; mi < 4; ++mi)
        #pragma unroll
        for (int ni = 0; ni < 4; ++ni)
            #pragma unroll
            for (int q = 0; q < 4; ++q) acc[mi][ni][q] = 0.f;

    const int br = tid >> 3;
    const int bu = tid & 7;
    auto stageB = [&](int s, int c) {
        #pragma unroll
        for (int pass = 0; pass < 4; ++pass) {
            const int row = pass * 32 + br;
            const uint32_t d = sb + s * STAGEBYTES + row * PITCHB + bu * 16;
            const size_t o = (size_t)(ntile * TN + row) * K_SZ + c * KC + bu * 8;
            cp_async16(d + B_HI, g_whi + o);
            cp_async16(d + B_LO, g_wlo + o);
        }
    };
    auto ldgA = [&](int c, float4* r) {
        #pragma unroll
        for (int i = 0; i < 8; ++i) {
            int v = tid + 256 * i;
            int row = v >> 4, seg = v & 15;
            r[i] = *reinterpret_cast<const float4*>(
                x + (size_t)(mtile * TM + row) * K_SZ + c * KC + seg * 4);
        }
    };
    auto stsA = [&](int s, const float4* r) {
        #pragma unroll
        for (int i = 0; i < 8; ++i) {
            int v = tid + 256 * i;
            int row = v >> 4, seg = v & 15;
            uint2 ph, pl;
            split2(r[i].x, r[i].y, ph.x, pl.x);
            split2(r[i].z, r[i].w, ph.y, pl.y);
            char* d = smem + s * STAGEBYTES + row * PITCHB + seg * 8;
            *reinterpret_cast<uint2*>(d + A_HI) = ph;
            *reinterpret_cast<uint2*>(d + A_LO) = pl;
        }
    };

    float4 ra[8];
    ldgA(0, ra);
    stageB(0, 0);
    CP_COMMIT();
    stsA(0, ra);

    for (int c = 0; c < NCHUNK; ++c) {
        const int s = c & 1;
        float4 rn[8];
        if (c + 1 < NCHUNK) {
            ldgA(c + 1, rn);
            stageB(s ^ 1, c + 1);
            CP_COMMIT();
            asm volatile("cp.async.wait_group 1;" ::: "memory");
        } else {
            asm volatile("cp.async.wait_group 0;" ::: "memory");
        }
        __syncthreads();

        const uint32_t base = sb + s * STAGEBYTES;
        #pragma unroll
        for (int kk = 0; kk < 4; ++kk) {
            uint32_t ah[4][4], al[4][4];
            #pragma unroll
            for (int mi = 0; mi < 4; ++mi) {
                uint32_t addr = base + (uint32_t)((wm * 64 + mi * 16) * PITCHB + kk * 32) + laneoff;
                ldmx4(ah[mi], addr + A_HI);
                ldmx4(al[mi], addr + A_LO);
            }
            uint32_t bh[4][2], bl[4][2];
            #pragma unroll
            for (int p = 0; p < 2; ++p) {
                uint32_t addr = base + (uint32_t)((wn * 32 + p * 16) * PITCHB + kk * 32) + laneoff;
                uint32_t r[4];
                ldmx4(r, addr + B_HI);
                bh[2*p][0] = r[0]; bh[2*p][1] = r[2];
                bh[2*p+1][0] = r[1]; bh[2*p+1][1] = r[3];
                ldmx4(r, addr + B_LO);
                bl[2*p][0] = r[0]; bl[2*p][1] = r[2];
                bl[2*p+1][0] = r[1]; bl[2*p+1][1] = r[3];
            }
            #pragma unroll
            for (int mi = 0; mi < 4; ++mi)
                #pragma unroll
                for (int ni = 0; ni < 4; ++ni) {
                    mma_bf16(acc[mi][ni], ah[mi], bh[ni]);
                    mma_bf16(acc[mi][ni], ah[mi], bl[ni]);
                    mma_bf16(acc[mi][ni], al[mi], bh[ni]);
                }
        }

        if (c + 1 < NCHUNK)
            stsA(s ^ 1, rn);
        __syncthreads();
    }

    const int g  = lane >> 2;
    const int tg = lane & 3;
    #pragma unroll
    for (int mi = 0; mi < 4; ++mi) {
        const int m0 = mtile * TM + wm * 64 + mi * 16 + g;
        #pragma unroll
        for (int ni = 0; ni < 4; ++ni) {
            const int nc = ntile * TN + wn * 32 + ni * 8 + tg * 2;
            *reinterpret_cast<float2*>(&g_proj[(size_t)m0 * F_SZ + nc]) =
                make_float2(acc[mi][ni][0], acc[mi][ni][1]);
            *reinterpret_cast<float2*>(&g_proj[(size_t)(m0 + 8) * F_SZ + nc]) =
                make_float2(acc[mi][ni][2], acc[mi][ni][3]);
        }
    }
}

// ---------------- FFMA GEMM: proj[:, 384:512] exact fp32 ----------------
__global__ __launch_bounds__(F_THREADS, 1)
void snn_gemm_ffma(const float* __restrict__ x,     // [64000, 256]
                   const float* __restrict__ wts,   // [512, 256]
                   int mblk_base)
{
    extern __shared__ char smem[];
    const uint32_t sb = smem_u32(smem);
    const int tid = threadIdx.x;
    const int tx  = tid & 15;          // n group: pairs at 2*tx + 32j
    const int ty  = tid >> 4;          // m group: rows ty*8 .. +7
    const int mb  = blockIdx.x + mblk_base;
    const int m0  = ty * 8;

    unsigned long long acc[8][4];
    #pragma unroll
    for (int i = 0; i < 8; ++i)
        #pragma unroll
        for (int j = 0; j < 4; ++j) acc[i][j] = 0ULL;

    auto stageA = [&](int s, int c) {
        #pragma unroll
        for (int i = 0; i < 4; ++i) {
            int v = tid + F_THREADS * i;       // 0..511
            int row = v >> 3, seg = v & 7;
            cp_async16(sb + s * FSTAGE + row * FA_PITCH + seg * 16,
                       x + (size_t)(mb * FM + row) * K_SZ + c * FKC + seg * 4);
        }
    };
    auto ldgB = [&](int c, float4* r) {
        // thread owns column n = tid; iterates over k segments (uncoalesced,
        // but w slice is L2-resident after the first wave).
        #pragma unroll
        for (int i = 0; i < 8; ++i)
            r[i] = *reinterpret_cast<const float4*>(
                wts + (size_t)(FNBASE + tid) * K_SZ + c * FKC + i * 4);
    };
    auto stsB = [&](int s, const float4* r) {
        // B_s[k][n]: lane-per-n -> conflict-free STS.32, pitch 512.
        char* base = smem + s * FSTAGE + FA_BYTES + tid * 4;
        #pragma unroll
        for (int i = 0; i < 8; ++i) {
            *reinterpret_cast<float*>(base + (4 * i + 0) * FB_PITCH) = r[i].x;
            *reinterpret_cast<float*>(base + (4 * i + 1) * FB_PITCH) = r[i].y;
            *reinterpret_cast<float*>(base + (4 * i + 2) * FB_PITCH) = r[i].z;
            *reinterpret_cast<float*>(base + (4 * i + 3) * FB_PITCH) = r[i].w;
        }
    };

    float4 rb[8];
    stageA(0, 0);
    CP_COMMIT();
    ldgB(0, rb);
    stsB(0, rb);
    asm volatile("cp.async.wait_group 0;" ::: "memory");
    __syncthreads();

    for (int c = 0; c < K_SZ / FKC; ++c) {     // 8 chunks
        const int s = c & 1;
        float4 rn[8];
        if (c < 7) {
            stageA(s ^ 1, c + 1);
            CP_COMMIT();
            ldgB(c + 1, rn);
        }

        const char* As = smem + s * FSTAGE;
        const char* Bs = smem + s * FSTAGE + FA_BYTES;
        #pragma unroll
        for (int k = 0; k < FKC; ++k) {
            unsigned long long ad[8];
            #pragma unroll
            for (int i = 0; i < 8; ++i) {
                float a = *reinterpret_cast<const float*>(As + (m0 + i) * FA_PITCH + k * 4);
                ad[i] = pack2(a, a);
            }
            unsigned long long bp[4];
            #pragma unroll
            for (int j = 0; j < 4; ++j)
                bp[j] = *reinterpret_cast<const unsigned long long*>(
                    Bs + k * FB_PITCH + (2 * tx + 32 * j) * 4);
            #pragma unroll
            for (int i = 0; i < 8; ++i)
                #pragma unroll
                for (int j = 0; j < 4; ++j)
                    fma2(acc[i][j], ad[i], bp[j]);
        }

        if (c < 7) {
            stsB(s ^ 1, rn);
            asm volatile("cp.async.wait_group 0;" ::: "memory");
        }
        __syncthreads();
    }

    // Epilogue: exact fp32 results for cols 384..511
    #pragma unroll
    for (int i = 0; i < 8; ++i) {
        float* dst = g_proj + (size_t)(mb * FM + m0 + i) * F_SZ + FNBASE + 2 * tx;
        #pragma unroll
        for (int j = 0; j < 4; ++j) {
            float lo, hi;
            unpack2(acc[i][j], lo, hi);
            *reinterpret_cast<float2*>(dst + 32 * j) = make_float2(lo, hi);
        }
    }
}

// ---------------- LIF scan over [t0, t1) with state carry ----------------
__global__ __launch_bounds__(512, 1)
void snn_scan_part(int t0, int t1, int first, int last)
{
    const int n = blockIdx.x * 512 + threadIdx.x;
    const float* p = g_proj + n;
    float u, tr, cnt;
    if (first) { u = 0.f; tr = 0.f; cnt = 0.f; }
    else       { u = g_u[n]; tr = g_tr[n]; cnt = g_counts[n]; }

    #pragma unroll 1
    for (int t = t0; t < t1; t += 20) {
        float v[20];
        #pragma unroll
        for (int j = 0; j < 20; ++j)
            v[j] = __ldcs(p + (size_t)(t + j) * NEURONS);
        #pragma unroll
        for (int j = 0; j < 20; ++j) {
            tr = 0.95f * tr + v[j];
            u  = 0.90f * u + tr;
            if (u > 1.0f) { cnt += 1.0f; u = 0.0f; }
        }
    }

    if (last) {
        g_counts[n] = cnt;
    } else {
        g_u[n] = u; g_tr[n] = tr; g_counts[n] = cnt;
    }
}

// ---------------- decoder ----------------
__global__ __launch_bounds__(320, 1)
void snn_decode_kernel(const float* __restrict__ dec_w,
                       const float* __restrict__ dec_b,
                       float* __restrict__ out)
{
    const int b = blockIdx.x;
    const int c = threadIdx.x >> 5;
    const int l = threadIdx.x & 31;
    const float* cnt = g_counts + (size_t)b * F_SZ;
    const float* dwr = dec_w + (size_t)c * F_SZ;
    float s = 0.f;
    #pragma unroll
    for (int fi = l; fi < F_SZ; fi += 32)
        s += cnt[fi] * dwr[fi];
    #pragma unroll
    for (int o = 16; o > 0; o >>= 1)
        s += __shfl_down_sync(0xffffffffu, s, o);
    if (l == 0)
        out[b * C_SZ + c] = s + dec_b[c];
}

extern "C" void kernel_launch(void* const* d_in, const int* in_sizes, int n_in,
                              void* d_out, int out_size)
{
    const float* x     = (const float*)d_in[0];
    const float* wts   = (const float*)d_in[1];
    const float* dec_w = (const float*)d_in[2];
    const float* dec_b = (const float*)d_in[3];
    float* out = (float*)d_out;

    static uint2* p_whi = nullptr; static uint2* p_wlo = nullptr;
    static cudaStream_t s1 = nullptr, s2 = nullptr, s3 = nullptr;
    static cudaEvent_t e0, eHA, eFA, eSA, eH, eF;
    if (!p_whi) {
        // One-time init on the first (non-captured) correctness call.
        cudaGetSymbolAddress((void**)&p_whi, g_whi);
        cudaGetSymbolAddress((void**)&p_wlo, g_wlo);
        cudaFuncSetAttribute(snn_gemm_kernel,
                             cudaFuncAttributeMaxDynamicSharedMemorySize, SMEM_TOTAL);
        cudaFuncSetAttribute(snn_gemm_ffma,
                             cudaFuncAttributeMaxDynamicSharedMemorySize, F_SMEM);
        cudaStreamCreateWithFlags(&s1, cudaStreamNonBlocking);
        cudaStreamCreateWithFlags(&s2, cudaStreamNonBlocking);
        cudaStreamCreateWithFlags(&s3, cudaStreamNonBlocking);
        cudaEventCreateWithFlags(&e0,  cudaEventDisableTiming);
        cudaEventCreateWithFlags(&eHA, cudaEventDisableTiming);
        cudaEventCreateWithFlags(&eFA, cudaEventDisableTiming);
        cudaEventCreateWithFlags(&eSA, cudaEventDisableTiming);
        cudaEventCreateWithFlags(&eH,  cudaEventDisableTiming);
        cudaEventCreateWithFlags(&eF,  cudaEventDisableTiming);
    }

    // Root work on the capture (default) stream, then fork.
    const int nw4 = F_SZ * K_SZ / 4;
    convert_w_kernel<<<(nw4 + 255) / 256, 256>>>((const float4*)wts, p_whi, p_wlo, nw4);
    cudaEventRecord(e0, 0);

    // s1: HMMA GEMM (cols 0..383), split at mtile 400 for scan overlap.
    cudaStreamWaitEvent(s1, e0, 0);
    snn_gemm_kernel<<<dim3(T_SPLIT, H_NTILES), GT, SMEM_TOTAL, s1>>>(x, 0);
    cudaEventRecord(eHA, s1);
    snn_gemm_kernel<<<dim3(T_STEPS - T_SPLIT, H_NTILES), GT, SMEM_TOTAL, s1>>>(x, T_SPLIT);
    cudaEventRecord(eH, s1);

    // s2: FFMA GEMM (cols 384..511), split at block 800.
    cudaStreamWaitEvent(s2, e0, 0);
    snn_gemm_ffma<<<F_SPLIT, F_THREADS, F_SMEM, s2>>>(x, wts, 0);
    cudaEventRecord(eFA, s2);
    snn_gemm_ffma<<<F_BLOCKS - F_SPLIT, F_THREADS, F_SMEM, s2>>>(x, wts, F_SPLIT);
    cudaEventRecord(eF, s2);

    // s3: scan part A (t < 400) once both A-parts are done; overlaps B-parts.
    cudaStreamWaitEvent(s3, eHA, 0);
    cudaStreamWaitEvent(s3, eFA, 0);
    snn_scan_part<<<NEURONS / 512, 512, 0, s3>>>(0, T_SPLIT, 1, 0);
    cudaEventRecord(eSA, s3);

    // Join on the capture stream: scan part B + decode.
    cudaStreamWaitEvent(0, eH, 0);
    cudaStreamWaitEvent(0, eF, 0);
    cudaStreamWaitEvent(0, eSA, 0);
    snn_scan_part<<<NEURONS / 512, 512>>>(T_SPLIT, T_STEPS, 0, 1);
    snn_decode_kernel<<<B_SZ, 320>>>(dec_w, dec_b, out);
}

// round 11
// speedup vs baseline: 1.1592x; 1.1592x over previous
#include <cuda_runtime.h>
#include <cuda_bf16.h>
#include <cstdint>

// Problem constants
#define T_STEPS 500
#define B_SZ    128
#define K_SZ    256
#define F_SZ    512
#define C_SZ    10
#define MROWS   (T_STEPS * B_SZ)   // 64000
#define NEURONS (B_SZ * F_SZ)      // 65536

#define T_SPLIT 400                 // scan overlap split (multiple of 20)

// GEMM tiling: CTA 128x128, 8 warps of 64x32, KC=64.
#define TM 128
#define TN 128
#define KC 64
#define NCHUNK (K_SZ / KC)   // 4
#define GT 256

// Padded smem rows: 64 bf16 (128B) + 16B pad = 144 B
#define PITCHB     144
#define TILEBYTES  (128 * PITCHB)      // 18432
#define A_HI 0
#define A_LO TILEBYTES
#define B_HI (2 * TILEBYTES)
#define B_LO (3 * TILEBYTES)
#define STAGEBYTES (4 * TILEBYTES)     // 73728
#define SMEM_TOTAL (2 * STAGEBYTES)    // 147456

// Scratch
__device__ float g_proj[MROWS * F_SZ];            // 131 MB
__device__ float g_counts[NEURONS];
__device__ float g_u[NEURONS];
__device__ float g_tr[NEURONS];
__device__ __nv_bfloat16 g_whi[F_SZ * K_SZ];
__device__ __nv_bfloat16 g_wlo[F_SZ * K_SZ];

// ---------------- helpers ----------------
__device__ __forceinline__ uint32_t smem_u32(const void* p) {
    uint32_t a;
    asm("{ .reg .u64 t; cvta.to.shared.u64 t, %1; cvt.u32.u64 %0, t; }" : "=r"(a) : "l"(p));
    return a;
}
__device__ __forceinline__ void cp_async16(uint32_t dst, const void* src) {
    asm volatile("cp.async.cg.shared.global [%0], [%1], 16;" :: "r"(dst), "l"(src) : "memory");
}
#define CP_COMMIT() asm volatile("cp.async.commit_group;" ::: "memory")

__device__ __forceinline__ void ldmx4(uint32_t* r, uint32_t addr) {
    asm volatile("ldmatrix.sync.aligned.m8n8.x4.shared.b16 {%0,%1,%2,%3}, [%4];"
                 : "=r"(r[0]), "=r"(r[1]), "=r"(r[2]), "=r"(r[3]) : "r"(addr));
}
__device__ __forceinline__ void mma_bf16(float* c, const uint32_t* a, const uint32_t* b) {
    asm volatile(
        "mma.sync.aligned.m16n8k16.row.col.f32.bf16.bf16.f32 "
        "{%0,%1,%2,%3}, {%4,%5,%6,%7}, {%8,%9}, {%0,%1,%2,%3};"
        : "+f"(c[0]), "+f"(c[1]), "+f"(c[2]), "+f"(c[3])
        : "r"(a[0]), "r"(a[1]), "r"(a[2]), "r"(a[3]), "r"(b[0]), "r"(b[1]));
}
__device__ __forceinline__ void split2(float a, float b, uint32_t& hi, uint32_t& lo) {
    __nv_bfloat16 h0 = __float2bfloat16(a), h1 = __float2bfloat16(b);
    __nv_bfloat16 l0 = __float2bfloat16(a - __bfloat162float(h0));
    __nv_bfloat16 l1 = __float2bfloat16(b - __bfloat162float(h1));
    hi = (uint32_t)*(uint16_t*)&h0 | ((uint32_t)*(uint16_t*)&h1 << 16);
    lo = (uint32_t)*(uint16_t*)&l0 | ((uint32_t)*(uint16_t*)&l1 << 16);
}

// ---------------- Pass 0: W fp32 -> bf16 hi/lo (tiny) ----------------
__global__ void convert_w_kernel(const float4* __restrict__ wsrc,
                                 uint2* __restrict__ whi, uint2* __restrict__ wlo, int n4)
{
    int i = blockIdx.x * blockDim.x + threadIdx.x;
    if (i >= n4) return;
    float4 v = wsrc[i];
    uint2 ph, pl;
    split2(v.x, v.y, ph.x, pl.x);
    split2(v.z, v.w, ph.y, pl.y);
    whi[i] = ph;
    wlo[i] = pl;
}

// ---------------- Pass 1: GEMM proj = x @ W^T (A split in-kernel) ----------------
__global__ __launch_bounds__(GT, 1)
void snn_gemm_kernel(const float* __restrict__ x, int mbase)
{
    extern __shared__ char smem[];
    const uint32_t sb = smem_u32(smem);
    const int tid  = threadIdx.x;
    const int lane = tid & 31;
    const int wid  = tid >> 5;
    const int wm   = wid >> 2;
    const int wn   = wid & 3;
    const int mtile = blockIdx.x + mbase;
    const int ntile = blockIdx.y;

    const uint32_t laneoff = (uint32_t)((lane & 15) * PITCHB + (lane >> 4) * 16);

    float acc[4][4][4];
    #pragma unroll
    for (int mi = 0; mi < 4; ++mi)
        #pragma unroll
        for (int ni = 0; ni < 4; ++ni)
            #pragma unroll
            for (int q = 0; q < 4; ++q) acc[mi][ni][q] = 0.f;

    const int br = tid >> 3;
    const int bu = tid & 7;
    auto stageB = [&](int s, int c) {
        #pragma unroll
        for (int pass = 0; pass < 4; ++pass) {
            const int row = pass * 32 + br;
            const uint32_t d = sb + s * STAGEBYTES + row * PITCHB + bu * 16;
            const size_t o = (size_t)(ntile * TN + row) * K_SZ + c * KC + bu * 8;
            cp_async16(d + B_HI, g_whi + o);
            cp_async16(d + B_LO, g_wlo + o);
        }
    };
    auto ldgA = [&](int c, float4* r) {
        #pragma unroll
        for (int i = 0; i < 8; ++i) {
            int v = tid + 256 * i;
            int row = v >> 4, seg = v & 15;
            r[i] = *reinterpret_cast<const float4*>(
                x + (size_t)(mtile * TM + row) * K_SZ + c * KC + seg * 4);
        }
    };
    auto stsA = [&](int s, const float4* r) {
        #pragma unroll
        for (int i = 0; i < 8; ++i) {
            int v = tid + 256 * i;
            int row = v >> 4, seg = v & 15;
            uint2 ph, pl;
            split2(r[i].x, r[i].y, ph.x, pl.x);
            split2(r[i].z, r[i].w, ph.y, pl.y);
            char* d = smem + s * STAGEBYTES + row * PITCHB + seg * 8;
            *reinterpret_cast<uint2*>(d + A_HI) = ph;
            *reinterpret_cast<uint2*>(d + A_LO) = pl;
        }
    };

    float4 ra[8];
    ldgA(0, ra);
    stageB(0, 0);
    CP_COMMIT();
    stsA(0, ra);

    for (int c = 0; c < NCHUNK; ++c) {
        const int s = c & 1;
        float4 rn[8];
        if (c + 1 < NCHUNK) {
            ldgA(c + 1, rn);
            stageB(s ^ 1, c + 1);
            CP_COMMIT();
            asm volatile("cp.async.wait_group 1;" ::: "memory");
        } else {
            asm volatile("cp.async.wait_group 0;" ::: "memory");
        }
        __syncthreads();

        const uint32_t base = sb + s * STAGEBYTES;
        #pragma unroll
        for (int kk = 0; kk < 4; ++kk) {
            uint32_t ah[4][4], al[4][4];
            #pragma unroll
            for (int mi = 0; mi < 4; ++mi) {
                uint32_t addr = base + (uint32_t)((wm * 64 + mi * 16) * PITCHB + kk * 32) + laneoff;
                ldmx4(ah[mi], addr + A_HI);
                ldmx4(al[mi], addr + A_LO);
            }
            uint32_t bh[4][2], bl[4][2];
            #pragma unroll
            for (int p = 0; p < 2; ++p) {
                uint32_t addr = base + (uint32_t)((wn * 32 + p * 16) * PITCHB + kk * 32) + laneoff;
                uint32_t r[4];
                ldmx4(r, addr + B_HI);
                bh[2*p][0] = r[0]; bh[2*p][1] = r[2];
                bh[2*p+1][0] = r[1]; bh[2*p+1][1] = r[3];
                ldmx4(r, addr + B_LO);
                bl[2*p][0] = r[0]; bl[2*p][1] = r[2];
                bl[2*p+1][0] = r[1]; bl[2*p+1][1] = r[3];
            }
            #pragma unroll
            for (int mi = 0; mi < 4; ++mi)
                #pragma unroll
                for (int ni = 0; ni < 4; ++ni) {
                    mma_bf16(acc[mi][ni], ah[mi], bh[ni]);
                    mma_bf16(acc[mi][ni], ah[mi], bl[ni]);
                    mma_bf16(acc[mi][ni], al[mi], bh[ni]);
                }
        }

        if (c + 1 < NCHUNK)
            stsA(s ^ 1, rn);
        __syncthreads();
    }

    const int g  = lane >> 2;
    const int tg = lane & 3;
    #pragma unroll
    for (int mi = 0; mi < 4; ++mi) {
        const int m0 = mtile * TM + wm * 64 + mi * 16 + g;
        #pragma unroll
        for (int ni = 0; ni < 4; ++ni) {
            const int nc = ntile * TN + wn * 32 + ni * 8 + tg * 2;
            *reinterpret_cast<float2*>(&g_proj[(size_t)m0 * F_SZ + nc]) =
                make_float2(acc[mi][ni][0], acc[mi][ni][1]);
            *reinterpret_cast<float2*>(&g_proj[(size_t)(m0 + 8) * F_SZ + nc]) =
                make_float2(acc[mi][ni][2], acc[mi][ni][3]);
        }
    }
}

// ---------------- Pass 2: LIF scan over [t0, t1) with state carry ----------------
__global__ __launch_bounds__(512, 1)
void snn_scan_part(int t0, int t1, int first, int last)
{
    const int n = blockIdx.x * 512 + threadIdx.x;
    const float* p = g_proj + n;
    float u, tr, cnt;
    if (first) { u = 0.f; tr = 0.f; cnt = 0.f; }
    else       { u = g_u[n]; tr = g_tr[n]; cnt = g_counts[n]; }

    #pragma unroll 1
    for (int t = t0; t < t1; t += 20) {          // ranges are multiples of 20
        float v[20];
        #pragma unroll
        for (int j = 0; j < 20; ++j)
            v[j] = __ldcs(p + (size_t)(t + j) * NEURONS);
        #pragma unroll
        for (int j = 0; j < 20; ++j) {
            tr = 0.95f * tr + v[j];
            u  = 0.90f * u + tr;
            if (u > 1.0f) { cnt += 1.0f; u = 0.0f; }
        }
    }

    if (last) {
        g_counts[n] = cnt;
    } else {
        g_u[n] = u; g_tr[n] = tr; g_counts[n] = cnt;
    }
}

// ---------------- Pass 3: decoder ----------------
__global__ __launch_bounds__(320, 1)
void snn_decode_kernel(const float* __restrict__ dec_w,
                       const float* __restrict__ dec_b,
                       float* __restrict__ out)
{
    const int b = blockIdx.x;
    const int c = threadIdx.x >> 5;
    const int l = threadIdx.x & 31;
    const float* cnt = g_counts + (size_t)b * F_SZ;
    const float* dwr = dec_w + (size_t)c * F_SZ;
    float s = 0.f;
    #pragma unroll
    for (int fi = l; fi < F_SZ; fi += 32)
        s += cnt[fi] * dwr[fi];
    #pragma unroll
    for (int o = 16; o > 0; o >>= 1)
        s += __shfl_down_sync(0xffffffffu, s, o);
    if (l == 0)
        out[b * C_SZ + c] = s + dec_b[c];
}

extern "C" void kernel_launch(void* const* d_in, const int* in_sizes, int n_in,
                              void* d_out, int out_size)
{
    const float* x     = (const float*)d_in[0];
    const float* wts   = (const float*)d_in[1];
    const float* dec_w = (const float*)d_in[2];
    const float* dec_b = (const float*)d_in[3];
    float* out = (float*)d_out;

    static uint2* p_whi = nullptr; static uint2* p_wlo = nullptr;
    static cudaStream_t s1 = nullptr, s2 = nullptr;
    static cudaEvent_t e0, eHA, eSA, eH;
    if (!p_whi) {
        // One-time init on the first (non-captured) correctness call.
        cudaGetSymbolAddress((void**)&p_whi, g_whi);
        cudaGetSymbolAddress((void**)&p_wlo, g_wlo);
        cudaFuncSetAttribute(snn_gemm_kernel,
                             cudaFuncAttributeMaxDynamicSharedMemorySize, SMEM_TOTAL);
        cudaStreamCreateWithFlags(&s1, cudaStreamNonBlocking);
        cudaStreamCreateWithFlags(&s2, cudaStreamNonBlocking);
        cudaEventCreateWithFlags(&e0,  cudaEventDisableTiming);
        cudaEventCreateWithFlags(&eHA, cudaEventDisableTiming);
        cudaEventCreateWithFlags(&eSA, cudaEventDisableTiming);
        cudaEventCreateWithFlags(&eH,  cudaEventDisableTiming);
    }

    // Root on the capture stream, then fork to explicit non-blocking streams.
    const int nw4 = F_SZ * K_SZ / 4;
    convert_w_kernel<<<(nw4 + 255) / 256, 256>>>((const float4*)wts, p_whi, p_wlo, nw4);
    cudaEventRecord(e0, 0);

    // s1: full GEMM (all 4 ntiles), split at mtile T_SPLIT for scan overlap.
    cudaStreamWaitEvent(s1, e0, 0);
    snn_gemm_kernel<<<dim3(T_SPLIT, F_SZ / TN), GT, SMEM_TOTAL, s1>>>(x, 0);
    cudaEventRecord(eHA, s1);
    snn_gemm_kernel<<<dim3(T_STEPS - T_SPLIT, F_SZ / TN), GT, SMEM_TOTAL, s1>>>(x, T_SPLIT);
    cudaEventRecord(eH, s1);

    // s2: scan part A (t < T_SPLIT) overlapping GEMM part B on s1.
    cudaStreamWaitEvent(s2, eHA, 0);
    snn_scan_part<<<NEURONS / 512, 512, 0, s2>>>(0, T_SPLIT, 1, 0);
    cudaEventRecord(eSA, s2);

    // Join on the capture stream: scan part B + decode.
    cudaStreamWaitEvent(0, eH, 0);
    cudaStreamWaitEvent(0, eSA, 0);
    snn_scan_part<<<NEURONS / 512, 512>>>(T_SPLIT, T_STEPS, 0, 1);
    snn_decode_kernel<<<B_SZ, 320>>>(dec_w, dec_b, out);
}